// round 1
// baseline (speedup 1.0000x reference)
#include <cuda_runtime.h>
#include <math.h>

#define NB 16
#define NN 64
#define VOL (NN*NN*NN)      // 262144
#define TOT (NB*VOL)        // 4194304
#define PITCH 65
#define PI_F 3.14159265358979323846f

// ---------------- scratch (device globals; no allocs allowed) ----------------
static __device__ float2 g_FX[TOT];   // spectrum of X_t (and later combined/inverse)
static __device__ float2 g_FY[TOT];   // spectrum of Y
static __device__ float  g_AM[NB][12];  // rotation (9) + translation (3) for mask warps
static __device__ float  g_AX[NB][12];  // for padded-X warp

// ---------------- complex helpers ----------------
__device__ __forceinline__ float2 cmul(float2 a, float2 b) {
    return make_float2(a.x * b.x - a.y * b.y, a.x * b.y + a.y * b.x);
}

// ---------------- register FFT-8 (natural in / natural out) ----------------
template <bool INV>
__device__ __forceinline__ void fft8(float2* v) {
    float2 t;
    // bit-reverse input: swap (1,4), (3,6)
    t = v[1]; v[1] = v[4]; v[4] = t;
    t = v[3]; v[3] = v[6]; v[6] = t;
    // stage 1
#pragma unroll
    for (int g = 0; g < 8; g += 2) {
        t = v[g + 1];
        v[g + 1] = make_float2(v[g].x - t.x, v[g].y - t.y);
        v[g]     = make_float2(v[g].x + t.x, v[g].y + t.y);
    }
    // stage 2 (twiddle w4^1 = -i fwd / +i inv)
#pragma unroll
    for (int g = 0; g < 8; g += 4) {
        t = v[g + 2];
        v[g + 2] = make_float2(v[g].x - t.x, v[g].y - t.y);
        v[g]     = make_float2(v[g].x + t.x, v[g].y + t.y);
        float2 u = v[g + 3];
        float2 w = INV ? make_float2(-u.y, u.x) : make_float2(u.y, -u.x);
        v[g + 3] = make_float2(v[g + 1].x - w.x, v[g + 1].y - w.y);
        v[g + 1] = make_float2(v[g + 1].x + w.x, v[g + 1].y + w.y);
    }
    // stage 3 (twiddles w8^{0..3})
    const float r = 0.70710678118654752f;
    const float2 w1 = INV ? make_float2(r, r)    : make_float2(r, -r);
    const float2 w2 = INV ? make_float2(0.f, 1.f) : make_float2(0.f, -1.f);
    const float2 w3 = INV ? make_float2(-r, r)   : make_float2(-r, -r);
    t = v[4];
    v[4] = make_float2(v[0].x - t.x, v[0].y - t.y);
    v[0] = make_float2(v[0].x + t.x, v[0].y + t.y);
    t = cmul(v[5], w1);
    v[5] = make_float2(v[1].x - t.x, v[1].y - t.y);
    v[1] = make_float2(v[1].x + t.x, v[1].y + t.y);
    t = cmul(v[6], w2);
    v[6] = make_float2(v[2].x - t.x, v[2].y - t.y);
    v[2] = make_float2(v[2].x + t.x, v[2].y + t.y);
    t = cmul(v[7], w3);
    v[7] = make_float2(v[3].x - t.x, v[3].y - t.y);
    v[3] = make_float2(v[3].x + t.x, v[3].y + t.y);
}

// ---------------- 64-point FFT on all 64 lines of a shared tile -------------
// Block must be 512 threads. Tile is 64 x PITCH float2.
// ROW=true:  FFT along fast index (contiguous within a row).
// ROW=false: FFT along slow index (down a column).
// 64 = 8x8 Cooley-Tukey: X[k2 + 8*k1] = FFT8_{n1}( w64^{n1*k2} * FFT8_{n2}(x[n1+8*n2]) )
template <bool INV, bool ROW>
__device__ void fft64_tile(float2* tile) {
    const int r = threadIdx.x >> 3;   // line index 0..63
    const int j = threadIdx.x & 7;    // sub-group lane 0..7
    float2* line;
    int st;
    if (ROW) { line = tile + r * PITCH; st = 1; }
    else     { line = tile + r;         st = PITCH; }

    float2 v[8];
#pragma unroll
    for (int m = 0; m < 8; m++) v[m] = line[(j + 8 * m) * st];   // x[n1=j + 8*n2]
    fft8<INV>(v);                                                 // A[n1=j, k2]
#pragma unroll
    for (int k2 = 1; k2 < 8; k2++) {                              // * w64^{j*k2}
        float s, c;
        sincospif((INV ? 1.0f : -1.0f) * (float)(j * k2) * (1.0f / 32.0f), &s, &c);
        v[k2] = cmul(v[k2], make_float2(c, s));
    }
    __syncthreads();
#pragma unroll
    for (int k2 = 0; k2 < 8; k2++) line[(j + 8 * k2) * st] = v[k2];  // B at [n1 + 8*k2]
    __syncthreads();
#pragma unroll
    for (int n1 = 0; n1 < 8; n1++) v[n1] = line[(n1 + 8 * j) * st];  // gather over n1, k2=j
    fft8<INV>(v);                                                     // C[k1]
    __syncthreads();
#pragma unroll
    for (int k1 = 0; k1 < 8; k1++) line[(j + 8 * k1) * st] = v[k1];  // X[k2=j + 8*k1]
    __syncthreads();
}

// ---------------- affine matrix setup ----------------
// Reference: rm = (Rz(phi) * Ry(th) * Rz(psi))^T ; c = -rm * loc
__device__ void fill_affine(float* A, const float th[6], bool zero_t) {
    const float a0 = th[0] * (2.0f * PI_F) - PI_F;
    const float a1 = th[1] * (2.0f * PI_F) - PI_F;
    const float a2 = th[2] * (2.0f * PI_F) - PI_F;
    float c1, s1, c2, s2, c3, s3;
    sincosf(a0, &s1, &c1);
    sincosf(a1, &s2, &c2);
    sincosf(a2, &s3, &c3);
    // M = Rz(a0) * Ry(a1) * Rz(a2)
    float M[9];
    M[0] = c1 * c2 * c3 - s1 * s3;  M[1] = -c1 * c2 * s3 - s1 * c3;  M[2] = c1 * s2;
    M[3] = s1 * c2 * c3 + c1 * s3;  M[4] = -s1 * c2 * s3 + c1 * c3;  M[5] = s1 * s2;
    M[6] = -s2 * c3;                M[7] = s2 * s3;                  M[8] = c2;
    // R = M^T
    float R[9] = { M[0], M[3], M[6],
                   M[1], M[4], M[7],
                   M[2], M[5], M[8] };
    float loc[3] = {0.f, 0.f, 0.f};
    if (!zero_t) {
        loc[0] = th[3] * 2.0f - 1.0f;
        loc[1] = th[4] * 2.0f - 1.0f;
        loc[2] = th[5] * 2.0f - 1.0f;
    }
#pragma unroll
    for (int i = 0; i < 9; i++) A[i] = R[i];
#pragma unroll
    for (int i = 0; i < 3; i++)
        A[9 + i] = -(R[3 * i] * loc[0] + R[3 * i + 1] * loc[1] + R[3 * i + 2] * loc[2]);
}

__global__ void k_setup(const float* __restrict__ theta) {
    int b = threadIdx.x;
    if (b >= NB) return;
    float th[6];
#pragma unroll
    for (int i = 0; i < 6; i++) th[i] = theta[b * 6 + i];
    fill_affine(g_AM[b], th, true);
    // theta_r = (theta - 0.5) * scale + 0.5, scale = [1,1,1, 64/66, 64/66, 64/66]
    float thr[6];
    const float sc = 64.0f / 66.0f;
#pragma unroll
    for (int i = 0; i < 3; i++) thr[i] = th[i];
#pragma unroll
    for (int i = 3; i < 6; i++) thr[i] = (th[i] - 0.5f) * sc + 0.5f;
    fill_affine(g_AX[b], thr, false);
}

// ---------------- trilinear samplers (exact reference semantics) ------------
__device__ __forceinline__ float sample64(const float* __restrict__ img, const float* A,
                                          float gx, float gy, float gz) {
    float t0 = A[0] * gx + A[1] * gy + A[2] * gz + A[9];
    float t1 = A[3] * gx + A[4] * gy + A[5] * gz + A[10];
    float t2 = A[6] * gx + A[7] * gy + A[8] * gz + A[11];
    float px = (t0 + 1.0f) * 31.5f;
    float py = (t1 + 1.0f) * 31.5f;
    float pz = (t2 + 1.0f) * 31.5f;
    float fx0 = fminf(fmaxf(floorf(px), 0.f), 63.f);
    float fy0 = fminf(fmaxf(floorf(py), 0.f), 63.f);
    float fz0 = fminf(fmaxf(floorf(pz), 0.f), 63.f);
    int x0 = (int)fx0, y0 = (int)fy0, z0 = (int)fz0;
    int x1 = min(x0 + 1, 63), y1 = min(y0 + 1, 63), z1 = min(z0 + 1, 63);
    float dx = px - fx0, dy = py - fy0, dz = pz - fz0;
    float v000 = img[(x0 * 64 + y0) * 64 + z0];
    float v001 = img[(x0 * 64 + y0) * 64 + z1];
    float v010 = img[(x0 * 64 + y1) * 64 + z0];
    float v011 = img[(x0 * 64 + y1) * 64 + z1];
    float v100 = img[(x1 * 64 + y0) * 64 + z0];
    float v101 = img[(x1 * 64 + y0) * 64 + z1];
    float v110 = img[(x1 * 64 + y1) * 64 + z0];
    float v111 = img[(x1 * 64 + y1) * 64 + z1];
    float c00 = v000 + (v001 - v000) * dz;
    float c01 = v010 + (v011 - v010) * dz;
    float c10 = v100 + (v101 - v100) * dz;
    float c11 = v110 + (v111 - v110) * dz;
    float c0 = c00 + (c01 - c00) * dy;
    float c1 = c10 + (c11 - c10) * dy;
    return c0 + (c1 - c0) * dx;
}

__device__ __forceinline__ float fetchpad(const float* __restrict__ Xb, int a, int b, int c) {
    if ((unsigned)(a - 1) > 63u || (unsigned)(b - 1) > 63u || (unsigned)(c - 1) > 63u) return 0.f;
    return Xb[((a - 1) * 64 + (b - 1)) * 64 + (c - 1)];
}

// sample the implicitly padded (66^3) X volume
__device__ __forceinline__ float sampleX(const float* __restrict__ Xb, const float* A,
                                         float gx, float gy, float gz) {
    float t0 = A[0] * gx + A[1] * gy + A[2] * gz + A[9];
    float t1 = A[3] * gx + A[4] * gy + A[5] * gz + A[10];
    float t2 = A[6] * gx + A[7] * gy + A[8] * gz + A[11];
    float px = (t0 + 1.0f) * 32.5f;
    float py = (t1 + 1.0f) * 32.5f;
    float pz = (t2 + 1.0f) * 32.5f;
    float fx0 = fminf(fmaxf(floorf(px), 0.f), 65.f);
    float fy0 = fminf(fmaxf(floorf(py), 0.f), 65.f);
    float fz0 = fminf(fmaxf(floorf(pz), 0.f), 65.f);
    int x0 = (int)fx0, y0 = (int)fy0, z0 = (int)fz0;
    int x1 = min(x0 + 1, 65), y1 = min(y0 + 1, 65), z1 = min(z0 + 1, 65);
    float dx = px - fx0, dy = py - fy0, dz = pz - fz0;
    float v000 = fetchpad(Xb, x0, y0, z0);
    float v001 = fetchpad(Xb, x0, y0, z1);
    float v010 = fetchpad(Xb, x0, y1, z0);
    float v011 = fetchpad(Xb, x0, y1, z1);
    float v100 = fetchpad(Xb, x1, y0, z0);
    float v101 = fetchpad(Xb, x1, y0, z1);
    float v110 = fetchpad(Xb, x1, y1, z0);
    float v111 = fetchpad(Xb, x1, y1, z1);
    float c00 = v000 + (v001 - v000) * dz;
    float c01 = v010 + (v011 - v010) * dz;
    float c10 = v100 + (v101 - v100) * dz;
    float c11 = v110 + (v111 - v110) * dz;
    float c0 = c00 + (c01 - c00) * dy;
    float c1 = c10 + (c11 - c10) * dy;
    return c0 + (c1 - c0) * dx;
}

// ---------------- K1: warp masks -> d_out[TOT..3*TOT) ----------------
__global__ void k_warp_masks(const float* __restrict__ m1, const float* __restrict__ m2,
                             float* __restrict__ out) {
    const int which = blockIdx.y;                     // 0 -> m1/M1_t, 1 -> m2/M2_t
    const int e = blockIdx.x * 256 + threadIdx.x;     // element within TOT
    const int b = e >> 18;
    const int rem = e & (VOL - 1);
    const int i = rem >> 12, j = (rem >> 6) & 63, k = rem & 63;
    const float* A = g_AM[b];
    const float gx = (float)i * (2.0f / 63.0f) - 1.0f;
    const float gy = (float)j * (2.0f / 63.0f) - 1.0f;
    const float gz = (float)k * (2.0f / 63.0f) - 1.0f;
    const float* img = (which ? m2 : m1) + b * VOL;
    out[(which + 1) * TOT + e] = sample64(img, A, gx, gy, gz);
}

// ---------------- K2a: fused warp(X) + sign + 2D FFT(H,W) -> g_FX -----------
__global__ void __launch_bounds__(512) k_fwd_x(const float* __restrict__ X) {
    __shared__ float2 tile[64 * PITCH];
    const int b = blockIdx.x >> 6, d = blockIdx.x & 63;
    const float* A = g_AX[b];
    const float* Xb = X + b * VOL;
    const int h = threadIdx.x >> 3, j = threadIdx.x & 7;
    const float gx = (float)(d + 1) * (2.0f / 65.0f) - 1.0f;
    const float gy = (float)(h + 1) * (2.0f / 65.0f) - 1.0f;
#pragma unroll
    for (int m = 0; m < 8; m++) {
        const int w = j + 8 * m;
        const float gz = (float)(w + 1) * (2.0f / 65.0f) - 1.0f;
        float val = sampleX(Xb, A, gx, gy, gz);
        if ((d + h + w) & 1) val = -val;   // fftshift-in as sign modulation
        tile[h * PITCH + w] = make_float2(val, 0.f);
    }
    __syncthreads();
    fft64_tile<false, true>(tile);   // along W
    fft64_tile<false, false>(tile);  // along H
    float2* dst = g_FX + b * VOL + d * 4096;
    for (int idx = threadIdx.x; idx < 4096; idx += 512)
        dst[idx] = tile[(idx >> 6) * PITCH + (idx & 63)];
}

// ---------------- K2b: sign + 2D FFT(H,W) of Y -> g_FY ----------------
__global__ void __launch_bounds__(512) k_fwd_y(const float* __restrict__ Y) {
    __shared__ float2 tile[64 * PITCH];
    const int b = blockIdx.x >> 6, d = blockIdx.x & 63;
    const float* Yb = Y + b * VOL + d * 4096;
    const int h = threadIdx.x >> 3, j = threadIdx.x & 7;
#pragma unroll
    for (int m = 0; m < 8; m++) {
        const int w = j + 8 * m;
        float val = Yb[h * 64 + w];
        if ((d + h + w) & 1) val = -val;
        tile[h * PITCH + w] = make_float2(val, 0.f);
    }
    __syncthreads();
    fft64_tile<false, true>(tile);
    fft64_tile<false, false>(tile);
    float2* dst = g_FY + b * VOL + d * 4096;
    for (int idx = threadIdx.x; idx < 4096; idx += 512)
        dst[idx] = tile[(idx >> 6) * PITCH + (idx & 63)];
}

// ---------------- K3: forward FFT along D for both arrays ----------------
__global__ void __launch_bounds__(512) k_fwd_d() {
    __shared__ float2 tile[64 * PITCH];
    const int b = blockIdx.x >> 6, h = blockIdx.x & 63;
    float2* g = (blockIdx.y ? g_FY : g_FX) + b * VOL + h * 64;
    for (int idx = threadIdx.x; idx < 4096; idx += 512) {
        const int dd = idx >> 6, ww = idx & 63;
        tile[ww * PITCH + dd] = g[dd * 4096 + ww];   // transpose: rows = fixed w, along d
    }
    __syncthreads();
    fft64_tile<false, true>(tile);
    for (int idx = threadIdx.x; idx < 4096; idx += 512) {
        const int dd = idx >> 6, ww = idx & 63;
        g[dd * 4096 + ww] = tile[ww * PITCH + dd];
    }
}

// ---------------- K4: combine (+spectral sign) + inverse FFT along D --------
__global__ void __launch_bounds__(512) k_comb_inv_d(const float* __restrict__ outp) {
    __shared__ float2 tile[64 * PITCH];
    const int b = blockIdx.x >> 6, h = blockIdx.x & 63;
    float2* fx = g_FX + b * VOL + h * 64;
    const float2* fy = g_FY + b * VOL + h * 64;
    const float* M1 = outp + TOT + b * VOL + h * 64;
    const float* M2 = outp + 2 * TOT + b * VOL + h * 64;
    for (int idx = threadIdx.x; idx < 4096; idx += 512) {
        const int dd = idx >> 6, ww = idx & 63;
        const int off = dd * 4096 + ww;
        const float2 a = fx[off];
        const float2 y = fy[off];
        const float m1v = M1[off];
        const float m2v = M2[off];
        float s = ((dd + h + ww) & 1) ? -1.0f : 1.0f;   // fftshift-out as spectral sign
        tile[ww * PITCH + dd] = make_float2((a.x * m1v + y.x * m2v) * s,
                                            (a.y * m1v + y.y * m2v) * s);
    }
    __syncthreads();
    fft64_tile<true, true>(tile);   // inverse along D (unscaled)
    for (int idx = threadIdx.x; idx < 4096; idx += 512) {
        const int dd = idx >> 6, ww = idx & 63;
        fx[dd * 4096 + ww] = tile[ww * PITCH + dd];
    }
}

// ---------------- K5: inverse FFT along W,H + scale + real -> d_out[0..TOT) -
__global__ void __launch_bounds__(512) k_inv_hw(float* __restrict__ out) {
    __shared__ float2 tile[64 * PITCH];
    const int b = blockIdx.x >> 6, d = blockIdx.x & 63;
    const float2* g = g_FX + b * VOL + d * 4096;
    for (int idx = threadIdx.x; idx < 4096; idx += 512)
        tile[(idx >> 6) * PITCH + (idx & 63)] = g[idx];
    __syncthreads();
    fft64_tile<true, true>(tile);   // along W
    fft64_tile<true, false>(tile);  // along H
    float* dst = out + b * VOL + d * 4096;
    const float scale = 1.0f / (float)VOL;
    for (int idx = threadIdx.x; idx < 4096; idx += 512)
        dst[idx] = tile[(idx >> 6) * PITCH + (idx & 63)].x * scale;
}

// ---------------- launch ----------------
extern "C" void kernel_launch(void* const* d_in, const int* in_sizes, int n_in,
                              void* d_out, int out_size) {
    const float* X     = (const float*)d_in[0];
    const float* Y     = (const float*)d_in[1];
    const float* m1    = (const float*)d_in[2];
    const float* m2    = (const float*)d_in[3];
    const float* theta = (const float*)d_in[4];
    float* out = (float*)d_out;

    k_setup<<<1, 32>>>(theta);
    k_warp_masks<<<dim3(TOT / 256, 2), 256>>>(m1, m2, out);
    k_fwd_x<<<NB * 64, 512>>>(X);
    k_fwd_y<<<NB * 64, 512>>>(Y);
    k_fwd_d<<<dim3(NB * 64, 2), 512>>>();
    k_comb_inv_d<<<NB * 64, 512>>>(out);
    k_inv_hw<<<NB * 64, 512>>>(out);
}

// round 2
// speedup vs baseline: 1.2330x; 1.2330x over previous
#include <cuda_runtime.h>
#include <math.h>

#define NB 16
#define NN 64
#define VOL (NN*NN*NN)      // 262144
#define TOT (NB*VOL)        // 4194304
#define PITCH 65
#define PI_F 3.14159265358979323846f

// ---------------- scratch (device globals; no allocs allowed) ----------------
static __device__ float2 g_FX[TOT];   // spectrum of X_t (and later combined/inverse)
static __device__ float2 g_FY[TOT];   // spectrum of Y
static __device__ float  g_AM[NB][12];
static __device__ float  g_AX[NB][12];

// ---------------- complex helpers ----------------
__device__ __forceinline__ float2 cmul(float2 a, float2 b) {
    return make_float2(a.x * b.x - a.y * b.y, a.x * b.y + a.y * b.x);
}

// ---------------- register FFT-8 (natural in / natural out) ----------------
template <bool INV>
__device__ __forceinline__ void fft8(float2* v) {
    float2 t;
    t = v[1]; v[1] = v[4]; v[4] = t;
    t = v[3]; v[3] = v[6]; v[6] = t;
#pragma unroll
    for (int g = 0; g < 8; g += 2) {
        t = v[g + 1];
        v[g + 1] = make_float2(v[g].x - t.x, v[g].y - t.y);
        v[g]     = make_float2(v[g].x + t.x, v[g].y + t.y);
    }
#pragma unroll
    for (int g = 0; g < 8; g += 4) {
        t = v[g + 2];
        v[g + 2] = make_float2(v[g].x - t.x, v[g].y - t.y);
        v[g]     = make_float2(v[g].x + t.x, v[g].y + t.y);
        float2 u = v[g + 3];
        float2 w = INV ? make_float2(-u.y, u.x) : make_float2(u.y, -u.x);
        v[g + 3] = make_float2(v[g + 1].x - w.x, v[g + 1].y - w.y);
        v[g + 1] = make_float2(v[g + 1].x + w.x, v[g + 1].y + w.y);
    }
    const float r = 0.70710678118654752f;
    const float2 w1 = INV ? make_float2(r, r)     : make_float2(r, -r);
    const float2 w2 = INV ? make_float2(0.f, 1.f) : make_float2(0.f, -1.f);
    const float2 w3 = INV ? make_float2(-r, r)    : make_float2(-r, -r);
    t = v[4];
    v[4] = make_float2(v[0].x - t.x, v[0].y - t.y);
    v[0] = make_float2(v[0].x + t.x, v[0].y + t.y);
    t = cmul(v[5], w1);
    v[5] = make_float2(v[1].x - t.x, v[1].y - t.y);
    v[1] = make_float2(v[1].x + t.x, v[1].y + t.y);
    t = cmul(v[6], w2);
    v[6] = make_float2(v[2].x - t.x, v[2].y - t.y);
    v[2] = make_float2(v[2].x + t.x, v[2].y + t.y);
    t = cmul(v[7], w3);
    v[7] = make_float2(v[3].x - t.x, v[3].y - t.y);
    v[3] = make_float2(v[3].x + t.x, v[3].y + t.y);
}

// ---------------- twiddle: v[k] *= w64^{+-j*k}, one MUFU + chain ------------
template <bool INV>
__device__ __forceinline__ void twiddle64(float2* v, int j) {
    float s, c;
    sincospif((INV ? 1.0f : -1.0f) * (float)j * (1.0f / 32.0f), &s, &c);
    float2 w = make_float2(c, s), wk = w;
#pragma unroll
    for (int k = 1; k < 8; k++) {
        v[k] = cmul(v[k], wk);
        wk = cmul(wk, w);
    }
}

// ---------------- 64-pt FFT; exchange through 'slot' region (warp-local) ----
// v holds x[j + 8*m] on entry; X[j + 8*k1] on exit (thread j of an 8-group).
// Exchange slots: thread j writes element k at (8j + ((k+j)&7))*st, reads
// element n at (8n + ((j+n)&7))*st  -> conflict-free-ish, warp-local sync only.
template <bool INV>
__device__ __forceinline__ void fft64_line(float2* slot, int st, int j, float2* v) {
    fft8<INV>(v);
    twiddle64<INV>(v, j);
    __syncwarp();
#pragma unroll
    for (int k = 0; k < 8; k++) slot[(8 * j + ((k + j) & 7)) * st] = v[k];
    __syncwarp();
#pragma unroll
    for (int n = 0; n < 8; n++) v[n] = slot[(8 * n + ((j + n) & 7)) * st];
    __syncwarp();
    fft8<INV>(v);
}

// Variant with a stride-9 conflict-free scratch region (72 float2 per group).
template <bool INV>
__device__ __forceinline__ void fft64_scr(float2* S, int j, float2* v) {
    fft8<INV>(v);
    twiddle64<INV>(v, j);
    __syncwarp();
#pragma unroll
    for (int k = 0; k < 8; k++) S[9 * j + k] = v[k];
    __syncwarp();
#pragma unroll
    for (int n = 0; n < 8; n++) v[n] = S[9 * n + j];
    __syncwarp();
    fft8<INV>(v);
}

// ---------------- affine matrix setup ----------------
__device__ void fill_affine(float* A, const float th[6], bool zero_t) {
    const float a0 = th[0] * (2.0f * PI_F) - PI_F;
    const float a1 = th[1] * (2.0f * PI_F) - PI_F;
    const float a2 = th[2] * (2.0f * PI_F) - PI_F;
    float c1, s1, c2, s2, c3, s3;
    sincosf(a0, &s1, &c1);
    sincosf(a1, &s2, &c2);
    sincosf(a2, &s3, &c3);
    float M[9];
    M[0] = c1 * c2 * c3 - s1 * s3;  M[1] = -c1 * c2 * s3 - s1 * c3;  M[2] = c1 * s2;
    M[3] = s1 * c2 * c3 + c1 * s3;  M[4] = -s1 * c2 * s3 + c1 * c3;  M[5] = s1 * s2;
    M[6] = -s2 * c3;                M[7] = s2 * s3;                  M[8] = c2;
    float R[9] = { M[0], M[3], M[6],
                   M[1], M[4], M[7],
                   M[2], M[5], M[8] };
    float loc[3] = {0.f, 0.f, 0.f};
    if (!zero_t) {
        loc[0] = th[3] * 2.0f - 1.0f;
        loc[1] = th[4] * 2.0f - 1.0f;
        loc[2] = th[5] * 2.0f - 1.0f;
    }
#pragma unroll
    for (int i = 0; i < 9; i++) A[i] = R[i];
#pragma unroll
    for (int i = 0; i < 3; i++)
        A[9 + i] = -(R[3 * i] * loc[0] + R[3 * i + 1] * loc[1] + R[3 * i + 2] * loc[2]);
}

__global__ void k_setup(const float* __restrict__ theta) {
    int b = threadIdx.x;
    if (b >= NB) return;
    float th[6];
#pragma unroll
    for (int i = 0; i < 6; i++) th[i] = theta[b * 6 + i];
    fill_affine(g_AM[b], th, true);
    float thr[6];
    const float sc = 64.0f / 66.0f;
#pragma unroll
    for (int i = 0; i < 3; i++) thr[i] = th[i];
#pragma unroll
    for (int i = 3; i < 6; i++) thr[i] = (th[i] - 0.5f) * sc + 0.5f;
    fill_affine(g_AX[b], thr, false);
}

// ---------------- trilinear samplers (exact reference semantics) ------------
__device__ __forceinline__ float sample64(const float* __restrict__ img, const float* A,
                                          float gx, float gy, float gz) {
    float t0 = A[0] * gx + A[1] * gy + A[2] * gz + A[9];
    float t1 = A[3] * gx + A[4] * gy + A[5] * gz + A[10];
    float t2 = A[6] * gx + A[7] * gy + A[8] * gz + A[11];
    float px = (t0 + 1.0f) * 31.5f;
    float py = (t1 + 1.0f) * 31.5f;
    float pz = (t2 + 1.0f) * 31.5f;
    float fx0 = fminf(fmaxf(floorf(px), 0.f), 63.f);
    float fy0 = fminf(fmaxf(floorf(py), 0.f), 63.f);
    float fz0 = fminf(fmaxf(floorf(pz), 0.f), 63.f);
    int x0 = (int)fx0, y0 = (int)fy0, z0 = (int)fz0;
    int x1 = min(x0 + 1, 63), y1 = min(y0 + 1, 63), z1 = min(z0 + 1, 63);
    float dx = px - fx0, dy = py - fy0, dz = pz - fz0;
    float v000 = img[(x0 * 64 + y0) * 64 + z0];
    float v001 = img[(x0 * 64 + y0) * 64 + z1];
    float v010 = img[(x0 * 64 + y1) * 64 + z0];
    float v011 = img[(x0 * 64 + y1) * 64 + z1];
    float v100 = img[(x1 * 64 + y0) * 64 + z0];
    float v101 = img[(x1 * 64 + y0) * 64 + z1];
    float v110 = img[(x1 * 64 + y1) * 64 + z0];
    float v111 = img[(x1 * 64 + y1) * 64 + z1];
    float c00 = v000 + (v001 - v000) * dz;
    float c01 = v010 + (v011 - v010) * dz;
    float c10 = v100 + (v101 - v100) * dz;
    float c11 = v110 + (v111 - v110) * dz;
    float c0 = c00 + (c01 - c00) * dy;
    float c1 = c10 + (c11 - c10) * dy;
    return c0 + (c1 - c0) * dx;
}

__device__ __forceinline__ float fetchpad(const float* __restrict__ Xb, int a, int b, int c) {
    if ((unsigned)(a - 1) > 63u || (unsigned)(b - 1) > 63u || (unsigned)(c - 1) > 63u) return 0.f;
    return Xb[((a - 1) * 64 + (b - 1)) * 64 + (c - 1)];
}

__device__ __forceinline__ float sampleX(const float* __restrict__ Xb, const float* A,
                                         float gx, float gy, float gz) {
    float t0 = A[0] * gx + A[1] * gy + A[2] * gz + A[9];
    float t1 = A[3] * gx + A[4] * gy + A[5] * gz + A[10];
    float t2 = A[6] * gx + A[7] * gy + A[8] * gz + A[11];
    float px = (t0 + 1.0f) * 32.5f;
    float py = (t1 + 1.0f) * 32.5f;
    float pz = (t2 + 1.0f) * 32.5f;
    float fx0 = fminf(fmaxf(floorf(px), 0.f), 65.f);
    float fy0 = fminf(fmaxf(floorf(py), 0.f), 65.f);
    float fz0 = fminf(fmaxf(floorf(pz), 0.f), 65.f);
    int x0 = (int)fx0, y0 = (int)fy0, z0 = (int)fz0;
    int x1 = min(x0 + 1, 65), y1 = min(y0 + 1, 65), z1 = min(z0 + 1, 65);
    float dx = px - fx0, dy = py - fy0, dz = pz - fz0;
    float v000 = fetchpad(Xb, x0, y0, z0);
    float v001 = fetchpad(Xb, x0, y0, z1);
    float v010 = fetchpad(Xb, x0, y1, z0);
    float v011 = fetchpad(Xb, x0, y1, z1);
    float v100 = fetchpad(Xb, x1, y0, z0);
    float v101 = fetchpad(Xb, x1, y0, z1);
    float v110 = fetchpad(Xb, x1, y1, z0);
    float v111 = fetchpad(Xb, x1, y1, z1);
    float c00 = v000 + (v001 - v000) * dz;
    float c01 = v010 + (v011 - v010) * dz;
    float c10 = v100 + (v101 - v100) * dz;
    float c11 = v110 + (v111 - v110) * dz;
    float c0 = c00 + (c01 - c00) * dy;
    float c1 = c10 + (c11 - c10) * dy;
    return c0 + (c1 - c0) * dx;
}

// ---------------- K1: warp masks -> d_out[TOT..3*TOT) ----------------
__global__ void k_warp_masks(const float* __restrict__ m1, const float* __restrict__ m2,
                             float* __restrict__ out) {
    const int which = blockIdx.y;
    const int e = blockIdx.x * 256 + threadIdx.x;
    const int b = e >> 18;
    const int rem = e & (VOL - 1);
    const int i = rem >> 12, j = (rem >> 6) & 63, k = rem & 63;
    const float* A = g_AM[b];
    const float gx = (float)i * (2.0f / 63.0f) - 1.0f;
    const float gy = (float)j * (2.0f / 63.0f) - 1.0f;
    const float gz = (float)k * (2.0f / 63.0f) - 1.0f;
    const float* img = (which ? m2 : m1) + b * VOL;
    out[(which + 1) * TOT + e] = sample64(img, A, gx, gy, gz);
}

// ---------------- K2a: fused warp(X) + sign + 2D FFT(H,W) -> g_FX -----------
__global__ void __launch_bounds__(512) k_fwd_x(const float* __restrict__ X) {
    __shared__ float2 tile[64 * PITCH];
    const int b = blockIdx.x >> 6, d = blockIdx.x & 63;
    const float* A = g_AX[b];
    const float* Xb = X + b * VOL;
    const int r = threadIdx.x >> 3, j = threadIdx.x & 7;
    const float gx = (float)(d + 1) * (2.0f / 65.0f) - 1.0f;
    const float gy = (float)(r + 1) * (2.0f / 65.0f) - 1.0f;
    float2 v[8];
#pragma unroll
    for (int m = 0; m < 8; m++) {
        const int w = j + 8 * m;
        const float gz = (float)(w + 1) * (2.0f / 65.0f) - 1.0f;
        float val = sampleX(Xb, A, gx, gy, gz);
        if ((d + r + w) & 1) val = -val;
        v[m] = make_float2(val, 0.f);
    }
    // row FFT along W (line r), exchange inside our own tile line
    fft64_line<false>(tile + r * PITCH, 1, j, v);
    __syncwarp();
#pragma unroll
    for (int k = 0; k < 8; k++) tile[r * PITCH + j + 8 * k] = v[k];
    __syncthreads();
    // column FFT along H (group owns column kw = r)
#pragma unroll
    for (int m = 0; m < 8; m++) v[m] = tile[(j + 8 * m) * PITCH + r];
    fft64_line<false>(tile + r, PITCH, j, v);
    float2* dst = g_FX + b * VOL + d * 4096;
#pragma unroll
    for (int k = 0; k < 8; k++) dst[(j + 8 * k) * 64 + r] = v[k];
}

// ---------------- K2b: sign + 2D FFT(H,W) of Y -> g_FY ----------------
__global__ void __launch_bounds__(512) k_fwd_y(const float* __restrict__ Y) {
    __shared__ float2 tile[64 * PITCH];
    const int b = blockIdx.x >> 6, d = blockIdx.x & 63;
    const float* Yb = Y + b * VOL + d * 4096;
    const int r = threadIdx.x >> 3, j = threadIdx.x & 7;
    float2 v[8];
#pragma unroll
    for (int m = 0; m < 8; m++) {
        const int w = j + 8 * m;
        float val = Yb[r * 64 + w];
        if ((d + r + w) & 1) val = -val;
        v[m] = make_float2(val, 0.f);
    }
    fft64_line<false>(tile + r * PITCH, 1, j, v);
    __syncwarp();
#pragma unroll
    for (int k = 0; k < 8; k++) tile[r * PITCH + j + 8 * k] = v[k];
    __syncthreads();
#pragma unroll
    for (int m = 0; m < 8; m++) v[m] = tile[(j + 8 * m) * PITCH + r];
    fft64_line<false>(tile + r, PITCH, j, v);
    float2* dst = g_FY + b * VOL + d * 4096;
#pragma unroll
    for (int k = 0; k < 8; k++) dst[(j + 8 * k) * 64 + r] = v[k];
}

// ---------------- K3: fused fwd-D(FX), fwd-D(FY), combine, inv-D ------------
// One (b,h) slab per block. Register-resident; global IO in 32B sectors.
__global__ void __launch_bounds__(512, 2) k_mid(const float* __restrict__ outp) {
    __shared__ float2 scr[64 * 72];   // 64 groups x (8x9) conflict-free exchange
    const int b = blockIdx.x >> 6, h = blockIdx.x & 63;
    const int g = threadIdx.x >> 3, j = threadIdx.x & 7;
    float2* S = scr + g * 72;
    const int base = b * VOL + h * 64 + g;   // + d*4096

    float2 a[8], v[8];
#pragma unroll
    for (int m = 0; m < 8; m++) a[m] = g_FX[base + (j + 8 * m) * 4096];
    fft64_scr<false>(S, j, a);            // FXhat[kd = j+8k]
#pragma unroll
    for (int m = 0; m < 8; m++) v[m] = g_FY[base + (j + 8 * m) * 4096];
    fft64_scr<false>(S, j, v);            // FYhat[kd = j+8k]

    const float* M1 = outp + TOT;
    const float* M2 = outp + 2 * TOT;
#pragma unroll
    for (int k = 0; k < 8; k++) {
        const int kd = j + 8 * k;
        const int off = b * VOL + kd * 4096 + h * 64 + g;
        const float m1v = __ldg(M1 + off);
        const float m2v = __ldg(M2 + off);
        const float s = ((kd + h + g) & 1) ? -1.0f : 1.0f;
        v[k] = make_float2((a[k].x * m1v + v[k].x * m2v) * s,
                           (a[k].y * m1v + v[k].y * m2v) * s);
    }
    fft64_scr<true>(S, j, v);             // inverse along D
#pragma unroll
    for (int k = 0; k < 8; k++) g_FX[base + (j + 8 * k) * 4096] = v[k];
}

// ---------------- K4: inverse FFT along W,H + scale + real -> d_out ---------
__global__ void __launch_bounds__(512) k_inv_hw(float* __restrict__ out) {
    __shared__ float2 tile[64 * PITCH];
    const int b = blockIdx.x >> 6, d = blockIdx.x & 63;
    const float2* gsl = g_FX + b * VOL + d * 4096;
    const int r = threadIdx.x >> 3, j = threadIdx.x & 7;
    float2 v[8];
#pragma unroll
    for (int m = 0; m < 8; m++) v[m] = gsl[r * 64 + j + 8 * m];
    fft64_line<true>(tile + r * PITCH, 1, j, v);   // inverse along W (line kh=r)
    __syncwarp();
#pragma unroll
    for (int k = 0; k < 8; k++) tile[r * PITCH + j + 8 * k] = v[k];
    __syncthreads();
#pragma unroll
    for (int m = 0; m < 8; m++) v[m] = tile[(j + 8 * m) * PITCH + r];
    fft64_line<true>(tile + r, PITCH, j, v);       // inverse along H (col kw=r)
    float* dst = out + b * VOL + d * 4096;
    const float sc = 1.0f / (float)VOL;
#pragma unroll
    for (int k = 0; k < 8; k++) dst[(j + 8 * k) * 64 + r] = v[k].x * sc;
}

// ---------------- launch ----------------
extern "C" void kernel_launch(void* const* d_in, const int* in_sizes, int n_in,
                              void* d_out, int out_size) {
    const float* X     = (const float*)d_in[0];
    const float* Y     = (const float*)d_in[1];
    const float* m1    = (const float*)d_in[2];
    const float* m2    = (const float*)d_in[3];
    const float* theta = (const float*)d_in[4];
    float* out = (float*)d_out;

    k_setup<<<1, 32>>>(theta);
    k_warp_masks<<<dim3(TOT / 256, 2), 256>>>(m1, m2, out);
    k_fwd_x<<<NB * 64, 512>>>(X);
    k_fwd_y<<<NB * 64, 512>>>(Y);
    k_mid<<<NB * 64, 512>>>(out);
    k_inv_hw<<<NB * 64, 512>>>(out);
}